// round 17
// baseline (speedup 1.0000x reference)
#include <cuda_runtime.h>
#include <cuda_fp16.h>
#include <cstdint>

#define NV 17
#define NC 64
#define NN 128
#define NB 64
#define NT 256
#define TILE_M 64

#define KPAD 72                       // A rows: 64 fp16 + 8 pad -> 144B, LDSM conflict-free
#define ROWB (KPAD * 2)

// smem byte offsets (single A tile + bias; B never touches smem)
#define SM_AH 0
#define SM_BIAS (SM_AH + TILE_M * ROWB)     // 9216
#define SMEM_BYTES (SM_BIAS + NN * 4)       // 9728

// B in fragment-direct layout: [v][n_blk(16)][ks(4)][lane(32)] of uint2{b0,b1} fp16x2
__device__ __align__(16) uint2 g_Wfrag[NV * 16 * 4 * 32];
__device__ __align__(16) float g_bias[NN];

__device__ __forceinline__ uint32_t smem_u32(const void* p) {
    uint32_t a;
    asm("{ .reg .u64 t; cvta.to.shared.u64 t, %1; cvt.u32.u64 %0, t; }" : "=r"(a) : "l"(p));
    return a;
}
__device__ __forceinline__ void ldsm_x4(uint32_t* r, uint32_t addr) {
    asm volatile("ldmatrix.sync.aligned.m8n8.x4.shared.b16 {%0,%1,%2,%3}, [%4];"
        : "=r"(r[0]), "=r"(r[1]), "=r"(r[2]), "=r"(r[3]) : "r"(addr));
}
__device__ __forceinline__ void mma_fp16(float* c, const uint32_t* a, const uint32_t* b) {
    asm volatile(
        "mma.sync.aligned.m16n8k16.row.col.f32.f16.f16.f32 "
        "{%0,%1,%2,%3}, {%4,%5,%6,%7}, {%8,%9}, {%0,%1,%2,%3};"
        : "+f"(c[0]), "+f"(c[1]), "+f"(c[2]), "+f"(c[3])
        : "r"(a[0]), "r"(a[1]), "r"(a[2]), "r"(a[3]), "r"(b[0]), "r"(b[1]));
}
__device__ __forceinline__ uint32_t packh(__half a, __half b) {
    __half2 h2 = __halves2half2(a, b);
    return *(uint32_t*)&h2;
}

// ---------------------------------------------------------------------------
// Prep: grid (NV, 4) — block (v, ks). All loads batched upfront; softmax
// without max-subtraction (|z| <= ~1, shift-invariant). Emits fp16 fragments.
// ---------------------------------------------------------------------------
__global__ void prep_kernel(const float* __restrict__ mat,
                            const float* __restrict__ amask,
                            const float* __restrict__ kern,
                            const float* __restrict__ gamma,
                            const float* __restrict__ beta,
                            const float* __restrict__ mean,
                            const float* __restrict__ var)
{
    const int v = blockIdx.x;
    const int ks = blockIdx.y;            // 0..3
    const int tid = threadIdx.x;          // 0..127
    const int lane = tid & 31, w = tid >> 5;
    __shared__ float aacc[4][NN];

    // batch-load all inputs for this warp's 5 m-rows (independent LDGs)
    float mt[5];
    float za[5][4];
    #pragma unroll
    for (int r = 0; r < 5; r++) {
        const int m = w + r * 4;
        const bool ok = m < NV;
        mt[r] = ok ? __ldg(&mat[m * NV + v]) : 0.f;
        #pragma unroll
        for (int j = 0; j < 4; j++)
            za[r][j] = ok ? __ldg(&amask[(m * NV + v) * NN + lane + j * 32]) : 0.f;
    }
    // batch-load the kern chunk too (overlaps with softmax below)
    float wv[16];
    #pragma unroll
    for (int i = 0; i < 16; i++)
        wv[i] = __ldg(&kern[(v * NC + ks * 16 + i) * NN + tid]);

    // softmax over n (no max-sub), per-warp partial a[n]
    #pragma unroll
    for (int r = 0; r < 5; r++) {
        const int m = w + r * 4;
        if (m < NV) {
            float e[4]; float s = 0.f;
            #pragma unroll
            for (int j = 0; j < 4; j++) { e[j] = expf(mt[r] * za[r][j]); s += e[j]; }
            #pragma unroll
            for (int o = 16; o > 0; o >>= 1)
                s += __shfl_xor_sync(0xffffffffu, s, o);
            const float inv = 1.f / s;
            #pragma unroll
            for (int j = 0; j < 4; j++) za[r][j] = e[j] * inv;
        } else {
            #pragma unroll
            for (int j = 0; j < 4; j++) za[r][j] = 0.f;
        }
    }
    #pragma unroll
    for (int j = 0; j < 4; j++) {
        float p = za[0][j] + za[1][j] + za[2][j] + za[3][j] + za[4][j];
        aacc[w][lane + j * 32] = p;
    }
    __syncthreads();

    const int n = tid;
    const float scale = gamma[n] * rsqrtf(var[n] + 1e-3f);
    const float an = (aacc[0][n] + aacc[1][n] + aacc[2][n] + aacc[3][n]) * scale;

    // fragments: lane l of n_blk holds rows n = n_blk*8 + l>>2,
    // k-pairs (l&3)*2 (+1), b1 at k+8; ks selects 16-wide k chunk.
    uint2* dst = g_Wfrag + ((size_t)v * 16 + (n >> 3)) * 4 * 32 + (n & 7) * 4 + ks * 32;
    __half h[16];
    #pragma unroll
    for (int i = 0; i < 16; i++) h[i] = __float2half_rn(wv[i] * an);
    #pragma unroll
    for (int q = 0; q < 4; q++) {
        uint2 u;
        u.x = packh(h[q*2],   h[q*2+1]);      // b0 (k, k+1)
        u.y = packh(h[q*2+8], h[q*2+9]);      // b1 (k+8, k+9)
        dst[q] = u;
    }
    if (v == 0 && ks == 0) g_bias[n] = beta[n] - mean[n] * scale;
}

// ---------------------------------------------------------------------------
// GEMM: CTA 64m x 128n for one v, K=64. 4 warps (2m x 2n), warp tile 32m x 64n.
// A single fp16 (rn), B fragments LDG'd inline from L2. 5 CTAs/SM, direct STG.
// ---------------------------------------------------------------------------
__global__ void __launch_bounds__(128, 5)
gemm_kernel(const float* __restrict__ x, float* __restrict__ out)
{
    extern __shared__ __align__(16) char smem[];
    const uint32_t sbase = smem_u32(smem);
    const int tid = threadIdx.x;
    const int wid = tid >> 5;              // 0..3
    const int lane = tid & 31;
    const int v = blockIdx.y;
    const int r0 = blockIdx.x * TILE_M;

    // --- Fill A tile, fully coalesced; single rn-fp16 ---
    #pragma unroll
    for (int i = 0; i < 8; i++) {
        const int c = tid + 128 * i;          // 0..1023
        const int m = c >> 4;
        const int ch = c & 15;
        const int r = r0 + m;
        const int b = r >> 8, t = r & 255;    // T = 256
        const float* p0 = x + (((size_t)(b * 2) * NT + t) * NV + v) * NC + ch * 4;
        float4 a0 = *(const float4*)p0;
        float4 a1 = *(const float4*)(p0 + (size_t)NT * NV * NC);
        __half2 h01 = __floats2half2_rn(a0.x + a1.x, a0.y + a1.y);
        __half2 h23 = __floats2half2_rn(a0.z + a1.z, a0.w + a1.w);
        uint2 ph;
        ph.x = *(uint32_t*)&h01; ph.y = *(uint32_t*)&h23;
        *(uint2*)(smem + SM_AH + m * ROWB + ch * 8) = ph;
    }
    // zero K pad (bytes 128..143 of each row) + bias
    if (tid < TILE_M)
        *(uint4*)(smem + SM_AH + tid * ROWB + 128) = make_uint4(0,0,0,0);
    ((float*)(smem + SM_BIAS))[tid] = g_bias[tid];
    __syncthreads();

    const int warp_m = (wid & 1) * 32;      // 2 m-groups
    const int warp_n = (wid >> 1) * 64;     // 2 n-groups (64 n each)
    const uint32_t a_lane = ((lane & 7) + ((lane >> 3) & 1) * 8) * ROWB
                          + ((lane >> 4) & 1) * 16;
    const uint32_t aBaseH = sbase + SM_AH + warp_m * ROWB + a_lane;
    const uint2* Bf = g_Wfrag + (((size_t)v * 16 + (wid >> 1) * 8) * 4) * 32 + lane;

    float acc[2][8][4];
    #pragma unroll
    for (int i = 0; i < 2; i++)
        #pragma unroll
        for (int j = 0; j < 8; j++)
            #pragma unroll
            for (int q = 0; q < 4; q++) acc[i][j][q] = 0.f;

    #pragma unroll
    for (int ks = 0; ks < 4; ks++) {
        uint32_t ah[2][4];
        #pragma unroll
        for (int mb = 0; mb < 2; mb++)
            ldsm_x4(ah[mb], aBaseH + mb * 16 * ROWB + ks * 32);
        #pragma unroll
        for (int nb = 0; nb < 8; nb++) {
            uint2 bu = __ldg(Bf + (nb * 4 + ks) * 32);
            #pragma unroll
            for (int mb = 0; mb < 2; mb++)
                mma_fp16(acc[mb][nb], ah[mb], &bu.x);
        }
    }

    // --- Epilogue: bias + ReLU + direct store (bias hoisted per nb) ---
    const float* bs = (const float*)(smem + SM_BIAS);
    const int qrow = lane >> 2;
    const int qcol = (lane & 3) * 2;
    #pragma unroll
    for (int nb = 0; nb < 8; nb++) {
        const int n = warp_n + nb * 8 + qcol;
        const float2 bb = *(const float2*)(bs + n);
        #pragma unroll
        for (int mb = 0; mb < 2; mb++) {
            const int mlo = warp_m + mb * 16 + qrow;
            float* o0 = out + ((size_t)(r0 + mlo) * NV + v) * NN + n;
            float* o1 = o0 + (size_t)8 * NV * NN;
            float2 r0v, r1v;
            r0v.x = fmaxf(acc[mb][nb][0] + bb.x, 0.f);
            r0v.y = fmaxf(acc[mb][nb][1] + bb.y, 0.f);
            r1v.x = fmaxf(acc[mb][nb][2] + bb.x, 0.f);
            r1v.y = fmaxf(acc[mb][nb][3] + bb.y, 0.f);
            *(float2*)o0 = r0v;
            *(float2*)o1 = r1v;
        }
    }
}

extern "C" void kernel_launch(void* const* d_in, const int* in_sizes, int n_in,
                              void* d_out, int out_size)
{
    const float* inputs = (const float*)d_in[0];
    const float* mat    = (const float*)d_in[1];
    const float* amask  = (const float*)d_in[2];
    const float* kern   = (const float*)d_in[3];
    const float* gamma  = (const float*)d_in[4];
    const float* beta   = (const float*)d_in[5];
    const float* mean   = (const float*)d_in[6];
    const float* var    = (const float*)d_in[7];
    float* out = (float*)d_out;

    cudaFuncSetAttribute(gemm_kernel,
                         cudaFuncAttributeMaxDynamicSharedMemorySize,
                         SMEM_BYTES);

    prep_kernel<<<dim3(NV, 4), NN>>>(mat, amask, kern, gamma, beta, mean, var);
    gemm_kernel<<<dim3((NB * NT) / TILE_M, NV), 128, SMEM_BYTES>>>(inputs, out);
}